// round 8
// baseline (speedup 1.0000x reference)
#include <cuda_runtime.h>
#include <cuda_fp16.h>
#include <cstdint>

// ---------------------------------------------------------------------------
// Problem dims (fixed by the dataset)
// ---------------------------------------------------------------------------
#define HDIM 4096
#define IDIM 14336
#define MDIM 4096   // BT * S = 2 * 2048
#define RNK  16

__constant__ float c_nf4[16] = {
  -1.0f, -0.6961928009986877f, -0.5250730514526367f, -0.39491748809814453f,
  -0.28444138169288635f, -0.18477343022823334f, -0.09105003625154495f, 0.0f,
  0.07958029955625534f, 0.16093020141124725f, 0.24611230194568634f,
  0.33791524171829224f, 0.44070982933044434f, 0.5626170039176941f,
  0.7229568362236023f, 1.0f};

// ---------------------------------------------------------------------------
// Scratch (static __device__ arrays: allocation-free per harness rules)
// ---------------------------------------------------------------------------
__device__ __half g_xh  [(size_t)MDIM * HDIM];
__device__ __half g_Wqkv[(size_t)HDIM * HDIM];
__device__ __half g_Wo  [(size_t)HDIM * HDIM];
__device__ __half g_Wgu [(size_t)2 * IDIM * HDIM];
__device__ __half g_Wd  [(size_t)HDIM * IDIM];
__device__ __half g_attn[(size_t)MDIM * HDIM];
__device__ __half g_x1h [(size_t)MDIM * HDIM];
__device__ float  g_x1f [(size_t)MDIM * HDIM];
__device__ __half g_gu  [(size_t)MDIM * 2 * IDIM];
__device__ __half g_hb  [(size_t)MDIM * IDIM];

// ---------------------------------------------------------------------------
// Dequant + LoRA-fold:  W[o,h] = mul * ( sum_j NF4[codes_j[o,h]]*scales_j[o,h/64]
//                                        + sum_r B[o,r]*A[r,h] )
// NSUM = 3 fuses q,k,v into one weight (mul = 1/3, rank 48 stacked adapter).
// ---------------------------------------------------------------------------
template<int NSUM>
__global__ void dq_kernel(const int* __restrict__ codes,
                          const float* __restrict__ scales,
                          const float* __restrict__ Amat,   // [16*NSUM, K] (planes contiguous)
                          const float* __restrict__ Bmat,   // [O, 16] per plane, plane stride bPlane
                          __half* __restrict__ W,
                          int O, int K,
                          long codePlane, long scalePlane, long bPlane,
                          float mul)
{
  constexpr int RR = 16 * NSUM;
  constexpr int HT = 256;
  constexpr int OT = 32;
  extern __shared__ float sA[];        // [RR][HT]
  __shared__ float sB[OT * 48];        // [OT][RR]
  const int tid = threadIdx.x;         // 256 threads
  const int h0 = blockIdx.x * HT;
  const int o0 = blockIdx.y * OT;

  for (int i = tid; i < RR * HT; i += 256) {
    int r = i / HT, c = i - r * HT;
    sA[i] = Amat[(long)r * K + h0 + c];
  }
  for (int i = tid; i < OT * RR; i += 256) {
    int oi = i / RR, r = i - oi * RR;
    sB[oi * RR + r] = Bmat[(long)(r >> 4) * bPlane + (long)(o0 + oi) * RNK + (r & 15)];
  }
  __syncthreads();

  const int h  = h0 + tid;
  const int hb = h >> 6;
  for (int oi = 0; oi < OT; ++oi) {
    const int o = o0 + oi;
    float acc = 0.f;
    #pragma unroll
    for (int j = 0; j < NSUM; ++j) {
      int   c = codes [(long)j * codePlane  + (long)o * K         + h];
      float s = scales[(long)j * scalePlane + (long)o * (K >> 6)  + hb];
      acc += c_nf4[c & 15] * s;
    }
    float lacc = 0.f;
    #pragma unroll
    for (int r = 0; r < RR; ++r) lacc += sB[oi * RR + r] * sA[r * HT + tid];
    W[(long)o * K + h] = __float2half((acc + lacc) * mul);
  }
}

// ---------------------------------------------------------------------------
// fp16 GEMM:  C[M,N] = A[M,K] @ B[N,K]^T  (both K-contiguous), fp32 accum.
// Tile 128x128x64, 8 warps (2x4), warp tile 64x32, mma.sync.m16n8k16,
// 3-stage cp.async pipeline, SW-style xor swizzle on 128B rows.
// EPI: 0 -> store half(C);  1 -> f = resid + C, store f32 + half;  2 -> f32 only.
// ---------------------------------------------------------------------------
#define BM 128
#define BN 128
#define BK 64
#define STG 3
#define SMEM_GEMM (STG * (BM + BN) * BK * 2)

__device__ __forceinline__ void cp16(uint32_t dst, const void* src) {
  asm volatile("cp.async.cg.shared.global [%0], [%1], 16;" :: "r"(dst), "l"(src));
}

__device__ __forceinline__ void gemm_load_stage(const __half* __restrict__ Ag,
                                                const __half* __restrict__ Bg,
                                                long Kdim, int m0, int n0,
                                                int lrow, int lcc,
                                                uint32_t sbase, int st, int kt)
{
  const long k0 = (long)kt * BK;
  uint32_t sA = sbase + (uint32_t)st * (BM + BN) * BK * 2u;
  uint32_t sB = sA + BM * BK * 2u;
  const __half* gA = Ag + (long)(m0 + lrow) * Kdim + k0 + lcc * 8;
  const __half* gB = Bg + (long)(n0 + lrow) * Kdim + k0 + lcc * 8;
  #pragma unroll
  for (int i = 0; i < 4; ++i) {
    int row = lrow + i * 32;
    uint32_t off = (uint32_t)row * 128u + ((uint32_t)(lcc ^ (row & 7)) << 4);
    cp16(sA + off, gA + (long)i * 32 * Kdim);
    cp16(sB + off, gB + (long)i * 32 * Kdim);
  }
  asm volatile("cp.async.commit_group;");
}

template<int EPI>
__global__ void __launch_bounds__(256, 1)
gemm_kernel(const __half* __restrict__ Ag, const __half* __restrict__ Bg,
            const float* __restrict__ Rg, __half* __restrict__ OH,
            float* __restrict__ OF, int Ndim, int Kdim)
{
  extern __shared__ __half smem[];
  const int tid  = threadIdx.x;
  const int m0   = blockIdx.x * BM;   // m fastest -> W n-band reused across wave (L2)
  const int n0   = blockIdx.y * BN;
  const uint32_t sbase = (uint32_t)__cvta_generic_to_shared(smem);
  const int warp = tid >> 5, lane = tid & 31;
  const int wm = warp & 1, wn = warp >> 1;
  const int lrow = tid >> 3, lcc = tid & 7;
  const int KT = Kdim / BK;

  float acc[4][4][4];
  #pragma unroll
  for (int a = 0; a < 4; ++a)
    #pragma unroll
    for (int b = 0; b < 4; ++b)
      #pragma unroll
      for (int c = 0; c < 4; ++c) acc[a][b][c] = 0.f;

  gemm_load_stage(Ag, Bg, Kdim, m0, n0, lrow, lcc, sbase, 0, 0);
  gemm_load_stage(Ag, Bg, Kdim, m0, n0, lrow, lcc, sbase, 1, 1);

  for (int kt = 0; kt < KT; ++kt) {
    if (kt + 1 < KT) asm volatile("cp.async.wait_group 1;");
    else             asm volatile("cp.async.wait_group 0;");
    __syncthreads();
    if (kt + 2 < KT)
      gemm_load_stage(Ag, Bg, Kdim, m0, n0, lrow, lcc, sbase, (kt + 2) % STG, kt + 2);

    uint32_t sA = sbase + (uint32_t)(kt % STG) * (BM + BN) * BK * 2u;
    uint32_t sB = sA + BM * BK * 2u;
    #pragma unroll
    for (int ks = 0; ks < 4; ++ks) {
      const int kk = ks * 16;
      uint32_t af[4][4];
      #pragma unroll
      for (int mi = 0; mi < 4; ++mi) {
        int row = wm * 64 + mi * 16 + (lane & 15);
        int col = kk + (lane >> 4) * 8;
        uint32_t addr = sA + (uint32_t)row * 128u +
                        ((uint32_t)(((col >> 3) ^ (row & 7))) << 4);
        asm volatile("ldmatrix.sync.aligned.m8n8.x4.shared.b16 {%0,%1,%2,%3}, [%4];"
                     : "=r"(af[mi][0]), "=r"(af[mi][1]), "=r"(af[mi][2]), "=r"(af[mi][3])
                     : "r"(addr));
      }
      uint32_t bf[4][2];
      #pragma unroll
      for (int nb = 0; nb < 2; ++nb) {
        int row = wn * 32 + nb * 16 + (lane & 7) + ((lane >> 4) << 3);
        int col = kk + ((lane >> 3) & 1) * 8;
        uint32_t addr = sB + (uint32_t)row * 128u +
                        ((uint32_t)(((col >> 3) ^ (row & 7))) << 4);
        asm volatile("ldmatrix.sync.aligned.m8n8.x4.shared.b16 {%0,%1,%2,%3}, [%4];"
                     : "=r"(bf[2*nb][0]), "=r"(bf[2*nb][1]),
                       "=r"(bf[2*nb+1][0]), "=r"(bf[2*nb+1][1])
                     : "r"(addr));
      }
      #pragma unroll
      for (int mi = 0; mi < 4; ++mi)
        #pragma unroll
        for (int ni = 0; ni < 4; ++ni)
          asm volatile("mma.sync.aligned.m16n8k16.row.col.f32.f16.f16.f32 "
                       "{%0,%1,%2,%3}, {%4,%5,%6,%7}, {%8,%9}, {%0,%1,%2,%3};"
                       : "+f"(acc[mi][ni][0]), "+f"(acc[mi][ni][1]),
                         "+f"(acc[mi][ni][2]), "+f"(acc[mi][ni][3])
                       : "r"(af[mi][0]), "r"(af[mi][1]), "r"(af[mi][2]), "r"(af[mi][3]),
                         "r"(bf[ni][0]), "r"(bf[ni][1]));
    }
  }

  // Epilogue (registers only, no sync needed)
  const long mbase = m0 + wm * 64 + (lane >> 2);
  const long nbase = n0 + wn * 32 + (lane & 3) * 2;
  #pragma unroll
  for (int mi = 0; mi < 4; ++mi) {
    #pragma unroll
    for (int ni = 0; ni < 4; ++ni) {
      long r = mbase + mi * 16;
      long c = nbase + ni * 8;
      long i0 = r * Ndim + c;
      long i1 = (r + 8) * Ndim + c;
      float v0 = acc[mi][ni][0], v1 = acc[mi][ni][1];
      float v2 = acc[mi][ni][2], v3 = acc[mi][ni][3];
      if (EPI >= 1) {
        float2 ra = *(const float2*)(Rg + i0);
        float2 rb = *(const float2*)(Rg + i1);
        v0 += ra.x; v1 += ra.y; v2 += rb.x; v3 += rb.y;
        *(float2*)(OF + i0) = make_float2(v0, v1);
        *(float2*)(OF + i1) = make_float2(v2, v3);
      }
      if (EPI <= 1) {
        *(__half2*)(OH + i0) = __floats2half2_rn(v0, v1);
        *(__half2*)(OH + i1) = __floats2half2_rn(v2, v3);
      }
    }
  }
}

// ---------------------------------------------------------------------------
// Elementwise kernels
// ---------------------------------------------------------------------------
__global__ void cvt_kernel(const float* __restrict__ x, __half* __restrict__ y) {
  long i = ((long)blockIdx.x * 256 + threadIdx.x) * 2;
  float2 v = *(const float2*)(x + i);
  *(__half2*)(y + i) = __floats2half2_rn(v.x, v.y);
}

__global__ void silu_kernel(const __half* __restrict__ gu, __half* __restrict__ ho) {
  const long m = blockIdx.y;
  const long c = ((long)blockIdx.x * 256 + threadIdx.x) * 2;
  const long base = m * (2L * IDIM);
  __half2 g2 = *(const __half2*)(gu + base + c);
  __half2 u2 = *(const __half2*)(gu + base + IDIM + c);
  float g0 = __half2float(__low2half(g2)), g1 = __half2float(__high2half(g2));
  float u0 = __half2float(__low2half(u2)), u1 = __half2float(__high2half(u2));
  float h0 = g0 / (1.f + __expf(-g0)) * u0;
  float h1 = g1 / (1.f + __expf(-g1)) * u1;
  *(__half2*)(ho + m * (long)IDIM + c) = __floats2half2_rn(h0, h1);
}

// ---------------------------------------------------------------------------
// Host driver (graph-capturable: kernel launches only)
// ---------------------------------------------------------------------------
extern "C" void kernel_launch(void* const* d_in, const int* in_sizes, int n_in,
                              void* d_out, int out_size) {
  const float* x           = (const float*)d_in[0];
  const int*   codes_attn  = (const int*)  d_in[1];
  const float* scales_attn = (const float*)d_in[2];
  const int*   codes_gu    = (const int*)  d_in[3];
  const float* scales_gu   = (const float*)d_in[4];
  const int*   codes_down  = (const int*)  d_in[5];
  const float* scales_down = (const float*)d_in[6];
  const float* lora_A_h    = (const float*)d_in[7];
  const float* lora_A_down = (const float*)d_in[8];
  const float* lora_B_attn = (const float*)d_in[9];
  const float* lora_B_gu   = (const float*)d_in[10];
  const float* lora_B_down = (const float*)d_in[11];
  (void)in_sizes; (void)n_in; (void)out_size;

  __half *xh, *Wqkv, *Wo, *Wgu, *Wd, *attn, *x1h, *gu, *hb;
  float *x1f;
  cudaGetSymbolAddress((void**)&xh,   g_xh);
  cudaGetSymbolAddress((void**)&Wqkv, g_Wqkv);
  cudaGetSymbolAddress((void**)&Wo,   g_Wo);
  cudaGetSymbolAddress((void**)&Wgu,  g_Wgu);
  cudaGetSymbolAddress((void**)&Wd,   g_Wd);
  cudaGetSymbolAddress((void**)&attn, g_attn);
  cudaGetSymbolAddress((void**)&x1h,  g_x1h);
  cudaGetSymbolAddress((void**)&x1f,  g_x1f);
  cudaGetSymbolAddress((void**)&gu,   g_gu);
  cudaGetSymbolAddress((void**)&hb,   g_hb);

  cudaFuncSetAttribute(gemm_kernel<0>, cudaFuncAttributeMaxDynamicSharedMemorySize, SMEM_GEMM);
  cudaFuncSetAttribute(gemm_kernel<1>, cudaFuncAttributeMaxDynamicSharedMemorySize, SMEM_GEMM);
  cudaFuncSetAttribute(gemm_kernel<2>, cudaFuncAttributeMaxDynamicSharedMemorySize, SMEM_GEMM);
  cudaFuncSetAttribute(dq_kernel<3>,   cudaFuncAttributeMaxDynamicSharedMemorySize, 48 * 256 * 4);

  // x -> fp16
  cvt_kernel<<<(MDIM * (long)HDIM) / 512, 256>>>(x, xh);

  // Dequant + LoRA fold (qkv fused with mul = 1/3)
  dim3 dqg_attn(HDIM / 256, HDIM / 32);
  dq_kernel<3><<<dqg_attn, 256, 48 * 256 * 4>>>(
      codes_attn, scales_attn, lora_A_h, lora_B_attn, Wqkv, HDIM, HDIM,
      (long)HDIM * HDIM, (long)HDIM * (HDIM / 64), (long)HDIM * RNK, 1.f / 3.f);
  dq_kernel<1><<<dqg_attn, 256, 16 * 256 * 4>>>(
      codes_attn + 3L * HDIM * HDIM, scales_attn + 3L * HDIM * (HDIM / 64),
      lora_A_h + 3L * RNK * HDIM, lora_B_attn + 3L * HDIM * RNK,
      Wo, HDIM, HDIM, 0, 0, 0, 1.f);
  dim3 dqg_gu(HDIM / 256, IDIM / 32);
  dq_kernel<1><<<dqg_gu, 256, 16 * 256 * 4>>>(
      codes_gu, scales_gu, lora_A_h + 4L * RNK * HDIM, lora_B_gu,
      Wgu, IDIM, HDIM, 0, 0, 0, 1.f);
  dq_kernel<1><<<dqg_gu, 256, 16 * 256 * 4>>>(
      codes_gu + (long)IDIM * HDIM, scales_gu + (long)IDIM * (HDIM / 64),
      lora_A_h + 5L * RNK * HDIM, lora_B_gu + (long)IDIM * RNK,
      Wgu + (long)IDIM * HDIM, IDIM, HDIM, 0, 0, 0, 1.f);
  dim3 dqg_d(IDIM / 256, HDIM / 32);
  dq_kernel<1><<<dqg_d, 256, 16 * 256 * 4>>>(
      codes_down, scales_down, lora_A_down, lora_B_down,
      Wd, HDIM, IDIM, 0, 0, 0, 1.f);

  // attn = xh @ Wqkv^T    (already = (q+k+v)/3)
  gemm_kernel<0><<<dim3(MDIM / 128, HDIM / 128), 256, SMEM_GEMM>>>(
      xh, Wqkv, nullptr, attn, nullptr, HDIM, HDIM);
  // x1 = x + attn @ Wo^T  (store fp32 + fp16)
  gemm_kernel<1><<<dim3(MDIM / 128, HDIM / 128), 256, SMEM_GEMM>>>(
      attn, Wo, x, x1h, x1f, HDIM, HDIM);
  // [g | u] = x1h @ Wgu^T
  gemm_kernel<0><<<dim3(MDIM / 128, (2 * IDIM) / 128), 256, SMEM_GEMM>>>(
      x1h, Wgu, nullptr, gu, nullptr, 2 * IDIM, HDIM);
  // h = silu(g) * u
  silu_kernel<<<dim3(IDIM / 512, MDIM), 256>>>(gu, hb);
  // out = x1 + h @ Wd^T   (fp32 to d_out)
  gemm_kernel<2><<<dim3(MDIM / 128, HDIM / 128), 256, SMEM_GEMM>>>(
      hb, Wd, x1f, nullptr, (float*)d_out, HDIM, IDIM);
}

// round 11
// speedup vs baseline: 1.0465x; 1.0465x over previous
#include <cuda_runtime.h>
#include <cuda_fp16.h>
#include <cstdint>

// ---------------------------------------------------------------------------
// Problem dims (fixed by the dataset)
// ---------------------------------------------------------------------------
#define HDIM 4096
#define IDIM 14336
#define MDIM 4096   // BT * S = 2 * 2048
#define RNK  16

__constant__ float c_nf4[16] = {
  -1.0f, -0.6961928009986877f, -0.5250730514526367f, -0.39491748809814453f,
  -0.28444138169288635f, -0.18477343022823334f, -0.09105003625154495f, 0.0f,
  0.07958029955625534f, 0.16093020141124725f, 0.24611230194568634f,
  0.33791524171829224f, 0.44070982933044434f, 0.5626170039176941f,
  0.7229568362236023f, 1.0f};

// ---------------------------------------------------------------------------
// Scratch (static __device__ arrays: allocation-free per harness rules)
// ---------------------------------------------------------------------------
__device__ __half g_xh  [(size_t)MDIM * HDIM];
__device__ __half g_Wqkv[(size_t)HDIM * HDIM];
__device__ __half g_Wo  [(size_t)HDIM * HDIM];
__device__ __half g_Wgu [(size_t)2 * IDIM * HDIM];
__device__ __half g_Wd  [(size_t)HDIM * IDIM];
__device__ __half g_attn[(size_t)MDIM * HDIM];
__device__ __half g_x1h [(size_t)MDIM * HDIM];
__device__ float  g_x1f [(size_t)MDIM * HDIM];
__device__ __half g_gu  [(size_t)MDIM * 2 * IDIM];
__device__ __half g_hb  [(size_t)MDIM * IDIM];

// ---------------------------------------------------------------------------
// Dequant + LoRA-fold, QKV-fused variant (3 code planes summed, mul=1/3).
// One h per thread; LoRA A in registers (rank 48 stacked).
// ---------------------------------------------------------------------------
__global__ void dq3_kernel(const int* __restrict__ codes,
                           const float* __restrict__ scales,
                           const float* __restrict__ Amat,   // [48, K]
                           const float* __restrict__ Bmat,   // [4, O, 16] planes
                           __half* __restrict__ W,
                           int O, int K,
                           long codePlane, long scalePlane, long bPlane,
                           float mul)
{
  constexpr int RR = 48;
  constexpr int OT = 32;
  __shared__ float sB[OT * RR];
  const int tid = threadIdx.x;         // 256 threads
  const int h0 = blockIdx.x * 256;
  const int o0 = blockIdx.y * OT;

  for (int i = tid; i < OT * RR; i += 256) {
    int oi = i / RR, r = i - oi * RR;
    sB[i] = Bmat[(long)(r >> 4) * bPlane + (long)(o0 + oi) * RNK + (r & 15)];
  }
  const int h = h0 + tid;
  float areg[RR];
  #pragma unroll
  for (int r = 0; r < RR; ++r) areg[r] = Amat[(long)r * K + h] * mul;
  __syncthreads();

  const int hb = h >> 6;
  #pragma unroll 4
  for (int oi = 0; oi < OT; ++oi) {
    const int o = o0 + oi;
    float acc = 0.f;
    #pragma unroll
    for (int j = 0; j < 3; ++j) {
      int   c = codes [(long)j * codePlane  + (long)o * K        + h];
      float s = scales[(long)j * scalePlane + (long)o * (K >> 6) + hb];
      acc += c_nf4[c & 15] * s;
    }
    acc *= mul;
    float lacc = 0.f;
    #pragma unroll
    for (int r = 0; r < RR; ++r) lacc += sB[oi * RR + r] * areg[r];
    W[(long)o * K + h] = __float2half(acc + lacc);
  }
}

// ---------------------------------------------------------------------------
// Dequant + LoRA-fold, single plane, 4 h per thread (int4 codes, float4 A,
// uint2 stores).  Block covers 1024 h x 32 o.
// ---------------------------------------------------------------------------
__global__ void dq1_kernel(const int* __restrict__ codes,
                           const float* __restrict__ scales,
                           const float* __restrict__ Amat,   // [16, K]
                           const float* __restrict__ Bmat,   // [O, 16]
                           __half* __restrict__ W,
                           int O, int K)
{
  constexpr int RR = 16;
  constexpr int OT = 32;
  __shared__ float sB[OT * RR];
  const int tid = threadIdx.x;         // 256 threads
  const int h0 = blockIdx.x * 1024;
  const int o0 = blockIdx.y * OT;

  for (int i = tid; i < OT * RR; i += 256) {
    int oi = i / RR, r = i - oi * RR;
    sB[i] = Bmat[(long)(o0 + oi) * RNK + r];
  }
  const int h = h0 + tid * 4;
  float4 areg[RR];
  #pragma unroll
  for (int r = 0; r < RR; ++r)
    areg[r] = *(const float4*)(Amat + (long)r * K + h);
  __syncthreads();

  const int hb = h >> 6;
  #pragma unroll 2
  for (int oi = 0; oi < OT; ++oi) {
    const int o = o0 + oi;
    int4  c4 = *(const int4*)(codes + (long)o * K + h);
    float s  = scales[(long)o * (K >> 6) + hb];
    float v0 = c_nf4[c4.x & 15] * s;
    float v1 = c_nf4[c4.y & 15] * s;
    float v2 = c_nf4[c4.z & 15] * s;
    float v3 = c_nf4[c4.w & 15] * s;
    #pragma unroll
    for (int r = 0; r < RR; ++r) {
      float b = sB[oi * RR + r];
      v0 += b * areg[r].x;
      v1 += b * areg[r].y;
      v2 += b * areg[r].z;
      v3 += b * areg[r].w;
    }
    __half2 lo = __floats2half2_rn(v0, v1);
    __half2 hi = __floats2half2_rn(v2, v3);
    uint2 pk;
    pk.x = *(uint32_t*)&lo;
    pk.y = *(uint32_t*)&hi;
    *(uint2*)(W + (long)o * K + h) = pk;
  }
}

// ---------------------------------------------------------------------------
// fp16 GEMM:  C[M,N] = A[M,K] @ B[N,K]^T  (both K-contiguous), fp32 accum.
// Tile 128x256x64, 8 warps (2x4), warp tile 64x64, mma.sync.m16n8k16,
// 3-stage cp.async pipeline, xor-swizzled 128B smem rows.
// EPI: 0 -> half(C);  1 -> f = resid + C, store f32 + half;  2 -> f32 only.
// ---------------------------------------------------------------------------
#define BM 128
#define BN 256
#define BK 64
#define STG 3
#define STAGE_B ((BM + BN) * BK * 2)          // 49152
#define SMEM_GEMM (STG * STAGE_B)             // 147456

__device__ __forceinline__ void cp16(uint32_t dst, const void* src) {
  asm volatile("cp.async.cg.shared.global [%0], [%1], 16;" :: "r"(dst), "l"(src));
}

__device__ __forceinline__ void gemm_load_stage(const __half* __restrict__ Ag,
                                                const __half* __restrict__ Bg,
                                                long Kdim, int m0, int n0,
                                                int lrow, int lcc,
                                                uint32_t sbase, int st, int kt)
{
  const long k0 = (long)kt * BK;
  uint32_t sA = sbase + (uint32_t)st * STAGE_B;
  uint32_t sB = sA + BM * BK * 2u;
  const __half* gA = Ag + (long)(m0 + lrow) * Kdim + k0 + lcc * 8;
  const __half* gB = Bg + (long)(n0 + lrow) * Kdim + k0 + lcc * 8;
  #pragma unroll
  for (int i = 0; i < 4; ++i) {           // 128 A rows / 32 row-groups
    int row = lrow + i * 32;
    uint32_t off = (uint32_t)row * 128u + ((uint32_t)(lcc ^ (row & 7)) << 4);
    cp16(sA + off, gA + (long)i * 32 * Kdim);
  }
  #pragma unroll
  for (int i = 0; i < 8; ++i) {           // 256 B rows
    int row = lrow + i * 32;
    uint32_t off = (uint32_t)row * 128u + ((uint32_t)(lcc ^ (row & 7)) << 4);
    cp16(sB + off, gB + (long)i * 32 * Kdim);
  }
  asm volatile("cp.async.commit_group;");
}

template<int EPI>
__global__ void __launch_bounds__(256, 1)
gemm_kernel(const __half* __restrict__ Ag, const __half* __restrict__ Bg,
            const float* __restrict__ Rg, __half* __restrict__ OH,
            float* __restrict__ OF, int Ndim, int Kdim)
{
  extern __shared__ __half smem[];
  const int tid  = threadIdx.x;
  const int m0   = blockIdx.x * BM;   // m fastest -> W n-band reused across wave
  const int n0   = blockIdx.y * BN;
  const uint32_t sbase = (uint32_t)__cvta_generic_to_shared(smem);
  const int warp = tid >> 5, lane = tid & 31;
  const int wm = warp & 1, wn = warp >> 1;          // 2 x 4 warps
  const int lrow = tid >> 3, lcc = tid & 7;
  const int KT = Kdim / BK;

  float acc[4][8][4];
  #pragma unroll
  for (int a = 0; a < 4; ++a)
    #pragma unroll
    for (int b = 0; b < 8; ++b)
      #pragma unroll
      for (int c = 0; c < 4; ++c) acc[a][b][c] = 0.f;

  gemm_load_stage(Ag, Bg, Kdim, m0, n0, lrow, lcc, sbase, 0, 0);
  gemm_load_stage(Ag, Bg, Kdim, m0, n0, lrow, lcc, sbase, 1, 1);

  for (int kt = 0; kt < KT; ++kt) {
    if (kt + 1 < KT) asm volatile("cp.async.wait_group 1;");
    else             asm volatile("cp.async.wait_group 0;");
    __syncthreads();
    if (kt + 2 < KT)
      gemm_load_stage(Ag, Bg, Kdim, m0, n0, lrow, lcc, sbase, (kt + 2) % STG, kt + 2);

    uint32_t sA = sbase + (uint32_t)(kt % STG) * STAGE_B;
    uint32_t sB = sA + BM * BK * 2u;
    #pragma unroll
    for (int ks = 0; ks < 4; ++ks) {
      const int kk = ks * 16;
      uint32_t af[4][4];
      #pragma unroll
      for (int mi = 0; mi < 4; ++mi) {
        int row = wm * 64 + mi * 16 + (lane & 15);
        int col = kk + (lane >> 4) * 8;
        uint32_t addr = sA + (uint32_t)row * 128u +
                        ((uint32_t)(((col >> 3) ^ (row & 7))) << 4);
        asm volatile("ldmatrix.sync.aligned.m8n8.x4.shared.b16 {%0,%1,%2,%3}, [%4];"
                     : "=r"(af[mi][0]), "=r"(af[mi][1]), "=r"(af[mi][2]), "=r"(af[mi][3])
                     : "r"(addr));
      }
      uint32_t bf[8][2];
      #pragma unroll
      for (int nb = 0; nb < 4; ++nb) {
        int row = wn * 64 + nb * 16 + (lane & 7) + ((lane >> 4) << 3);
        int col = kk + ((lane >> 3) & 1) * 8;
        uint32_t addr = sB + (uint32_t)row * 128u +
                        ((uint32_t)(((col >> 3) ^ (row & 7))) << 4);
        asm volatile("ldmatrix.sync.aligned.m8n8.x4.shared.b16 {%0,%1,%2,%3}, [%4];"
                     : "=r"(bf[2*nb][0]), "=r"(bf[2*nb][1]),
                       "=r"(bf[2*nb+1][0]), "=r"(bf[2*nb+1][1])
                     : "r"(addr));
      }
      #pragma unroll
      for (int mi = 0; mi < 4; ++mi)
        #pragma unroll
        for (int ni = 0; ni < 8; ++ni)
          asm volatile("mma.sync.aligned.m16n8k16.row.col.f32.f16.f16.f32 "
                       "{%0,%1,%2,%3}, {%4,%5,%6,%7}, {%8,%9}, {%0,%1,%2,%3};"
                       : "+f"(acc[mi][ni][0]), "+f"(acc[mi][ni][1]),
                         "+f"(acc[mi][ni][2]), "+f"(acc[mi][ni][3])
                       : "r"(af[mi][0]), "r"(af[mi][1]), "r"(af[mi][2]), "r"(af[mi][3]),
                         "r"(bf[ni][0]), "r"(bf[ni][1]));
    }
  }

  // Epilogue (registers only)
  const long mbase = m0 + wm * 64 + (lane >> 2);
  const long nbase = n0 + wn * 64 + (lane & 3) * 2;
  #pragma unroll
  for (int mi = 0; mi < 4; ++mi) {
    #pragma unroll
    for (int ni = 0; ni < 8; ++ni) {
      long r = mbase + mi * 16;
      long c = nbase + ni * 8;
      long i0 = r * Ndim + c;
      long i1 = (r + 8) * Ndim + c;
      float v0 = acc[mi][ni][0], v1 = acc[mi][ni][1];
      float v2 = acc[mi][ni][2], v3 = acc[mi][ni][3];
      if (EPI >= 1) {
        float2 ra = *(const float2*)(Rg + i0);
        float2 rb = *(const float2*)(Rg + i1);
        v0 += ra.x; v1 += ra.y; v2 += rb.x; v3 += rb.y;
        *(float2*)(OF + i0) = make_float2(v0, v1);
        *(float2*)(OF + i1) = make_float2(v2, v3);
      }
      if (EPI <= 1) {
        *(__half2*)(OH + i0) = __floats2half2_rn(v0, v1);
        *(__half2*)(OH + i1) = __floats2half2_rn(v2, v3);
      }
    }
  }
}

// ---------------------------------------------------------------------------
// Elementwise kernels
// ---------------------------------------------------------------------------
__global__ void cvt_kernel(const float* __restrict__ x, __half* __restrict__ y) {
  long i = ((long)blockIdx.x * 256 + threadIdx.x) * 2;
  float2 v = *(const float2*)(x + i);
  *(__half2*)(y + i) = __floats2half2_rn(v.x, v.y);
}

__global__ void silu_kernel(const __half* __restrict__ gu, __half* __restrict__ ho) {
  const long m = blockIdx.y;
  const long c = ((long)blockIdx.x * 256 + threadIdx.x) * 2;
  const long base = m * (2L * IDIM);
  __half2 g2 = *(const __half2*)(gu + base + c);
  __half2 u2 = *(const __half2*)(gu + base + IDIM + c);
  float g0 = __half2float(__low2half(g2)), g1 = __half2float(__high2half(g2));
  float u0 = __half2float(__low2half(u2)), u1 = __half2float(__high2half(u2));
  float h0 = g0 / (1.f + __expf(-g0)) * u0;
  float h1 = g1 / (1.f + __expf(-g1)) * u1;
  *(__half2*)(ho + m * (long)IDIM + c) = __floats2half2_rn(h0, h1);
}

// ---------------------------------------------------------------------------
// Host driver (graph-capturable: kernel launches only)
// ---------------------------------------------------------------------------
extern "C" void kernel_launch(void* const* d_in, const int* in_sizes, int n_in,
                              void* d_out, int out_size) {
  const float* x           = (const float*)d_in[0];
  const int*   codes_attn  = (const int*)  d_in[1];
  const float* scales_attn = (const float*)d_in[2];
  const int*   codes_gu    = (const int*)  d_in[3];
  const float* scales_gu   = (const float*)d_in[4];
  const int*   codes_down  = (const int*)  d_in[5];
  const float* scales_down = (const float*)d_in[6];
  const float* lora_A_h    = (const float*)d_in[7];
  const float* lora_A_down = (const float*)d_in[8];
  const float* lora_B_attn = (const float*)d_in[9];
  const float* lora_B_gu   = (const float*)d_in[10];
  const float* lora_B_down = (const float*)d_in[11];
  (void)in_sizes; (void)n_in; (void)out_size;

  __half *xh, *Wqkv, *Wo, *Wgu, *Wd, *attn, *x1h, *gu, *hb;
  float *x1f;
  cudaGetSymbolAddress((void**)&xh,   g_xh);
  cudaGetSymbolAddress((void**)&Wqkv, g_Wqkv);
  cudaGetSymbolAddress((void**)&Wo,   g_Wo);
  cudaGetSymbolAddress((void**)&Wgu,  g_Wgu);
  cudaGetSymbolAddress((void**)&Wd,   g_Wd);
  cudaGetSymbolAddress((void**)&attn, g_attn);
  cudaGetSymbolAddress((void**)&x1h,  g_x1h);
  cudaGetSymbolAddress((void**)&x1f,  g_x1f);
  cudaGetSymbolAddress((void**)&gu,   g_gu);
  cudaGetSymbolAddress((void**)&hb,   g_hb);

  cudaFuncSetAttribute(gemm_kernel<0>, cudaFuncAttributeMaxDynamicSharedMemorySize, SMEM_GEMM);
  cudaFuncSetAttribute(gemm_kernel<1>, cudaFuncAttributeMaxDynamicSharedMemorySize, SMEM_GEMM);
  cudaFuncSetAttribute(gemm_kernel<2>, cudaFuncAttributeMaxDynamicSharedMemorySize, SMEM_GEMM);

  // x -> fp16
  cvt_kernel<<<(MDIM * (long)HDIM) / 512, 256>>>(x, xh);

  // Dequant + LoRA fold (qkv fused with mul = 1/3)
  dq3_kernel<<<dim3(HDIM / 256, HDIM / 32), 256>>>(
      codes_attn, scales_attn, lora_A_h, lora_B_attn, Wqkv, HDIM, HDIM,
      (long)HDIM * HDIM, (long)HDIM * (HDIM / 64), (long)HDIM * RNK, 1.f / 3.f);
  dq1_kernel<<<dim3(HDIM / 1024, HDIM / 32), 256>>>(
      codes_attn + 3L * HDIM * HDIM, scales_attn + 3L * HDIM * (HDIM / 64),
      lora_A_h + 3L * RNK * HDIM, lora_B_attn + 3L * HDIM * RNK,
      Wo, HDIM, HDIM);
  dq1_kernel<<<dim3(HDIM / 1024, IDIM / 32), 256>>>(
      codes_gu, scales_gu, lora_A_h + 4L * RNK * HDIM, lora_B_gu,
      Wgu, IDIM, HDIM);
  dq1_kernel<<<dim3(HDIM / 1024, IDIM / 32), 256>>>(
      codes_gu + (long)IDIM * HDIM, scales_gu + (long)IDIM * (HDIM / 64),
      lora_A_h + 5L * RNK * HDIM, lora_B_gu + (long)IDIM * RNK,
      Wgu + (long)IDIM * HDIM, IDIM, HDIM);
  dq1_kernel<<<dim3(IDIM / 1024, HDIM / 32), 256>>>(
      codes_down, scales_down, lora_A_down, lora_B_down,
      Wd, HDIM, IDIM);

  // attn = xh @ Wqkv^T    (already = (q+k+v)/3)
  gemm_kernel<0><<<dim3(MDIM / BM, HDIM / BN), 256, SMEM_GEMM>>>(
      xh, Wqkv, nullptr, attn, nullptr, HDIM, HDIM);
  // x1 = x + attn @ Wo^T  (store fp32 + fp16)
  gemm_kernel<1><<<dim3(MDIM / BM, HDIM / BN), 256, SMEM_GEMM>>>(
      attn, Wo, x, x1h, x1f, HDIM, HDIM);
  // [g | u] = x1h @ Wgu^T
  gemm_kernel<0><<<dim3(MDIM / BM, (2 * IDIM) / BN), 256, SMEM_GEMM>>>(
      x1h, Wgu, nullptr, gu, nullptr, 2 * IDIM, HDIM);
  // h = silu(g) * u
  silu_kernel<<<dim3(IDIM / 512, MDIM), 256>>>(gu, hb);
  // out = x1 + h @ Wd^T   (fp32 to d_out)
  gemm_kernel<2><<<dim3(MDIM / BM, HDIM / BN), 256, SMEM_GEMM>>>(
      hb, Wd, x1f, nullptr, (float*)d_out, HDIM, IDIM);
}

// round 12
// speedup vs baseline: 1.1440x; 1.0932x over previous
#include <cuda_runtime.h>
#include <cuda_fp16.h>
#include <cstdint>

// ---------------------------------------------------------------------------
// Problem dims (fixed by the dataset)
// ---------------------------------------------------------------------------
#define HDIM 4096
#define IDIM 14336
#define MDIM 4096   // BT * S = 2 * 2048
#define RNK  16

__constant__ float c_nf4[16] = {
  -1.0f, -0.6961928009986877f, -0.5250730514526367f, -0.39491748809814453f,
  -0.28444138169288635f, -0.18477343022823334f, -0.09105003625154495f, 0.0f,
  0.07958029955625534f, 0.16093020141124725f, 0.24611230194568634f,
  0.33791524171829224f, 0.44070982933044434f, 0.5626170039176941f,
  0.7229568362236023f, 1.0f};

// ---------------------------------------------------------------------------
// Scratch (static __device__ arrays: allocation-free per harness rules)
// ---------------------------------------------------------------------------
__device__ __half g_xh  [(size_t)MDIM * HDIM];
__device__ __half g_Wqkv[(size_t)HDIM * HDIM];
__device__ __half g_Wo  [(size_t)HDIM * HDIM];
__device__ __half g_Wgu [(size_t)2 * IDIM * HDIM];
__device__ __half g_Wd  [(size_t)HDIM * IDIM];
__device__ __half g_attn[(size_t)MDIM * HDIM];
__device__ __half g_x1h [(size_t)MDIM * HDIM];
__device__ float  g_x1f [(size_t)MDIM * HDIM];
__device__ __half g_gu  [(size_t)MDIM * 2 * IDIM];
__device__ __half g_hb  [(size_t)MDIM * IDIM];

// ---------------------------------------------------------------------------
// Dequant + LoRA-fold, QKV-fused variant (3 code planes summed, mul=1/3).
// ---------------------------------------------------------------------------
__global__ void dq3_kernel(const int* __restrict__ codes,
                           const float* __restrict__ scales,
                           const float* __restrict__ Amat,   // [48, K]
                           const float* __restrict__ Bmat,   // [4, O, 16] planes
                           __half* __restrict__ W,
                           int O, int K,
                           long codePlane, long scalePlane, long bPlane,
                           float mul)
{
  constexpr int RR = 48;
  constexpr int OT = 32;
  __shared__ float sB[OT * RR];
  const int tid = threadIdx.x;         // 256 threads
  const int h0 = blockIdx.x * 256;
  const int o0 = blockIdx.y * OT;

  for (int i = tid; i < OT * RR; i += 256) {
    int oi = i / RR, r = i - oi * RR;
    sB[i] = Bmat[(long)(r >> 4) * bPlane + (long)(o0 + oi) * RNK + (r & 15)];
  }
  const int h = h0 + tid;
  float areg[RR];
  #pragma unroll
  for (int r = 0; r < RR; ++r) areg[r] = Amat[(long)r * K + h] * mul;
  __syncthreads();

  const int hb = h >> 6;
  #pragma unroll 4
  for (int oi = 0; oi < OT; ++oi) {
    const int o = o0 + oi;
    float acc = 0.f;
    #pragma unroll
    for (int j = 0; j < 3; ++j) {
      int   c = codes [(long)j * codePlane  + (long)o * K        + h];
      float s = scales[(long)j * scalePlane + (long)o * (K >> 6) + hb];
      acc += c_nf4[c & 15] * s;
    }
    acc *= mul;
    float lacc = 0.f;
    #pragma unroll
    for (int r = 0; r < RR; ++r) lacc += sB[oi * RR + r] * areg[r];
    W[(long)o * K + h] = __float2half(acc + lacc);
  }
}

// ---------------------------------------------------------------------------
// Dequant + LoRA-fold, single plane, 4 h per thread, 4-deep load rotation
// (int4 codes + scale prefetched 4 o-rows ahead -> MLP>=4, hides DRAM lat).
// ---------------------------------------------------------------------------
__global__ void dq1_kernel(const int* __restrict__ codes,
                           const float* __restrict__ scales,
                           const float* __restrict__ Amat,   // [16, K]
                           const float* __restrict__ Bmat,   // [O, 16]
                           __half* __restrict__ W,
                           int O, int K)
{
  constexpr int RR = 16;
  constexpr int OT = 32;
  __shared__ float sB[OT * RR];
  const int tid = threadIdx.x;         // 256 threads
  const int h0 = blockIdx.x * 1024;
  const int o0 = blockIdx.y * OT;

  for (int i = tid; i < OT * RR; i += 256) {
    int oi = i / RR, r = i - oi * RR;
    sB[i] = Bmat[(long)(o0 + oi) * RNK + r];
  }
  const int h = h0 + tid * 4;
  float4 areg[RR];
  #pragma unroll
  for (int r = 0; r < RR; ++r)
    areg[r] = *(const float4*)(Amat + (long)r * K + h);
  __syncthreads();

  const int hb = h >> 6;
  const int ks6 = K >> 6;

  int4  c[4];
  float s[4];
  #pragma unroll
  for (int j = 0; j < 4; ++j) {
    c[j] = *(const int4*)(codes + (long)(o0 + j) * K + h);
    s[j] = scales[(long)(o0 + j) * ks6 + hb];
  }

  #pragma unroll 4
  for (int oi = 0; oi < OT; ++oi) {
    const int slot = oi & 3;
    int4  cc = c[slot];
    float ss = s[slot];
    if (oi + 4 < OT) {
      c[slot] = *(const int4*)(codes + (long)(o0 + oi + 4) * K + h);
      s[slot] = scales[(long)(o0 + oi + 4) * ks6 + hb];
    }
    float v0 = c_nf4[cc.x & 15] * ss;
    float v1 = c_nf4[cc.y & 15] * ss;
    float v2 = c_nf4[cc.z & 15] * ss;
    float v3 = c_nf4[cc.w & 15] * ss;
    #pragma unroll
    for (int r = 0; r < RR; ++r) {
      float b = sB[oi * RR + r];
      v0 += b * areg[r].x;
      v1 += b * areg[r].y;
      v2 += b * areg[r].z;
      v3 += b * areg[r].w;
    }
    __half2 lo = __floats2half2_rn(v0, v1);
    __half2 hi = __floats2half2_rn(v2, v3);
    uint2 pk;
    pk.x = *(uint32_t*)&lo;
    pk.y = *(uint32_t*)&hi;
    *(uint2*)(W + (long)(o0 + oi) * K + h) = pk;
  }
}

// ---------------------------------------------------------------------------
// fp16 GEMM:  C[M,N] = A[M,K] @ B[N,K]^T  (both K-contiguous), fp32 accum.
// Tile 128x256x64, 8 warps (2x4), warp tile 64x64, mma.sync.m16n8k16.
// 3-stage cp.async pipeline; per-kt: double-buffered LDSM fragments
// (prefetch ks+1 before mma of ks) and next-stage cp.async spread over ks.
// EPI: 0 -> half(C);  1 -> f = resid + C, store f32 + half;  2 -> f32 only.
// ---------------------------------------------------------------------------
#define BM 128
#define BN 256
#define BK 64
#define STG 3
#define STAGE_B ((BM + BN) * BK * 2)          // 49152
#define SMEM_GEMM (STG * STAGE_B)             // 147456

__device__ __forceinline__ void cp16(uint32_t dst, const void* src) {
  asm volatile("cp.async.cg.shared.global [%0], [%1], 16;" :: "r"(dst), "l"(src));
}

// Prologue full-stage load (A 4 rows-groups + B 8) + commit.
__device__ __forceinline__ void gemm_load_stage(const __half* __restrict__ Ag,
                                                const __half* __restrict__ Bg,
                                                long Kdim, int m0, int n0,
                                                int lrow, int lcc, uint32_t off0,
                                                uint32_t sbase, int st, int kt)
{
  const long k0 = (long)kt * BK;
  uint32_t sA = sbase + (uint32_t)st * STAGE_B;
  uint32_t sB = sA + BM * BK * 2u;
  const __half* gA = Ag + (long)(m0 + lrow) * Kdim + k0 + lcc * 8;
  const __half* gB = Bg + (long)(n0 + lrow) * Kdim + k0 + lcc * 8;
  #pragma unroll
  for (int i = 0; i < 4; ++i)
    cp16(sA + off0 + (uint32_t)i * 4096u, gA + (long)i * 32 * Kdim);
  #pragma unroll
  for (int i = 0; i < 8; ++i)
    cp16(sB + off0 + (uint32_t)i * 4096u, gB + (long)i * 32 * Kdim);
  asm volatile("cp.async.commit_group;");
}

// Load one ks worth of fragments (A: 4 ldmatrix.x4, B: 4 ldmatrix.x4).
__device__ __forceinline__ void ld_frags(uint32_t sA, uint32_t sB,
                                         int wm, int wn, int lane, int ks,
                                         uint32_t af[4][4], uint32_t bf[8][2])
{
  #pragma unroll
  for (int mi = 0; mi < 4; ++mi) {
    int row = wm * 64 + mi * 16 + (lane & 15);
    int c3  = 2 * ks + (lane >> 4);
    uint32_t addr = sA + (uint32_t)row * 128u +
                    ((uint32_t)((c3 ^ (row & 7))) << 4);
    asm volatile("ldmatrix.sync.aligned.m8n8.x4.shared.b16 {%0,%1,%2,%3}, [%4];"
                 : "=r"(af[mi][0]), "=r"(af[mi][1]), "=r"(af[mi][2]), "=r"(af[mi][3])
                 : "r"(addr));
  }
  #pragma unroll
  for (int nb = 0; nb < 4; ++nb) {
    int row = wn * 64 + nb * 16 + (lane & 7) + ((lane >> 4) << 3);
    int c3  = 2 * ks + ((lane >> 3) & 1);
    uint32_t addr = sB + (uint32_t)row * 128u +
                    ((uint32_t)((c3 ^ (row & 7))) << 4);
    asm volatile("ldmatrix.sync.aligned.m8n8.x4.shared.b16 {%0,%1,%2,%3}, [%4];"
                 : "=r"(bf[2*nb][0]), "=r"(bf[2*nb][1]),
                   "=r"(bf[2*nb+1][0]), "=r"(bf[2*nb+1][1])
                 : "r"(addr));
  }
}

template<int EPI>
__global__ void __launch_bounds__(256, 1)
gemm_kernel(const __half* __restrict__ Ag, const __half* __restrict__ Bg,
            const float* __restrict__ Rg, __half* __restrict__ OH,
            float* __restrict__ OF, int Ndim, int Kdim)
{
  extern __shared__ __half smem[];
  const int tid  = threadIdx.x;
  const int m0   = blockIdx.x * BM;   // m fastest -> W n-band reused across wave
  const int n0   = blockIdx.y * BN;
  const uint32_t sbase = (uint32_t)__cvta_generic_to_shared(smem);
  const int warp = tid >> 5, lane = tid & 31;
  const int wm = warp & 1, wn = warp >> 1;          // 2 x 4 warps
  const int lrow = tid >> 3, lcc = tid & 7;
  const uint32_t off0 = (uint32_t)lrow * 128u +
                        ((uint32_t)(lcc ^ (lrow & 7)) << 4);
  const int KT = Kdim / BK;

  float acc[4][8][4];
  #pragma unroll
  for (int a = 0; a < 4; ++a)
    #pragma unroll
    for (int b = 0; b < 8; ++b)
      #pragma unroll
      for (int c = 0; c < 4; ++c) acc[a][b][c] = 0.f;

  gemm_load_stage(Ag, Bg, Kdim, m0, n0, lrow, lcc, off0, sbase, 0, 0);
  gemm_load_stage(Ag, Bg, Kdim, m0, n0, lrow, lcc, off0, sbase, 1, 1);

  uint32_t af[2][4][4], bf[2][8][2];

  for (int kt = 0; kt < KT; ++kt) {
    asm volatile("cp.async.wait_group 1;");
    __syncthreads();

    uint32_t sA = sbase + (uint32_t)(kt % STG) * STAGE_B;
    uint32_t sB = sA + BM * BK * 2u;

    // Next-stage global pointers (stage kt+2)
    const bool pf = (kt + 2 < KT);
    const long pk0 = (long)(kt + 2) * BK;
    uint32_t pA = sbase + (uint32_t)((kt + 2) % STG) * STAGE_B;
    uint32_t pB = pA + BM * BK * 2u;
    const __half* gA = Ag + (long)(m0 + lrow) * Kdim + pk0 + lcc * 8;
    const __half* gB = Bg + (long)(n0 + lrow) * Kdim + pk0 + lcc * 8;

    ld_frags(sA, sB, wm, wn, lane, 0, af[0], bf[0]);

    #pragma unroll
    for (int ks = 0; ks < 4; ++ks) {
      if (ks < 3)
        ld_frags(sA, sB, wm, wn, lane, ks + 1, af[(ks + 1) & 1], bf[(ks + 1) & 1]);
      if (ks == 0 && pf) {
        #pragma unroll
        for (int i = 0; i < 4; ++i)
          cp16(pA + off0 + (uint32_t)i * 4096u, gA + (long)i * 32 * Kdim);
      }
      if (ks == 1 && pf) {
        #pragma unroll
        for (int i = 0; i < 4; ++i)
          cp16(pB + off0 + (uint32_t)i * 4096u, gB + (long)i * 32 * Kdim);
      }
      if (ks == 2 && pf) {
        #pragma unroll
        for (int i = 4; i < 8; ++i)
          cp16(pB + off0 + (uint32_t)i * 4096u, gB + (long)i * 32 * Kdim);
      }
      if (ks == 3)
        asm volatile("cp.async.commit_group;");   // empty group at tail keeps count

      const int cb = ks & 1;
      #pragma unroll
      for (int mi = 0; mi < 4; ++mi)
        #pragma unroll
        for (int ni = 0; ni < 8; ++ni)
          asm volatile("mma.sync.aligned.m16n8k16.row.col.f32.f16.f16.f32 "
                       "{%0,%1,%2,%3}, {%4,%5,%6,%7}, {%8,%9}, {%0,%1,%2,%3};"
                       : "+f"(acc[mi][ni][0]), "+f"(acc[mi][ni][1]),
                         "+f"(acc[mi][ni][2]), "+f"(acc[mi][ni][3])
                       : "r"(af[cb][mi][0]), "r"(af[cb][mi][1]),
                         "r"(af[cb][mi][2]), "r"(af[cb][mi][3]),
                         "r"(bf[cb][ni][0]), "r"(bf[cb][ni][1]));
    }
  }

  // Epilogue (registers only)
  const long mbase = m0 + wm * 64 + (lane >> 2);
  const long nbase = n0 + wn * 64 + (lane & 3) * 2;
  #pragma unroll
  for (int mi = 0; mi < 4; ++mi) {
    #pragma unroll
    for (int ni = 0; ni < 8; ++ni) {
      long r = mbase + mi * 16;
      long c = nbase + ni * 8;
      long i0 = r * Ndim + c;
      long i1 = (r + 8) * Ndim + c;
      float v0 = acc[mi][ni][0], v1 = acc[mi][ni][1];
      float v2 = acc[mi][ni][2], v3 = acc[mi][ni][3];
      if (EPI >= 1) {
        float2 ra = *(const float2*)(Rg + i0);
        float2 rb = *(const float2*)(Rg + i1);
        v0 += ra.x; v1 += ra.y; v2 += rb.x; v3 += rb.y;
        *(float2*)(OF + i0) = make_float2(v0, v1);
        *(float2*)(OF + i1) = make_float2(v2, v3);
      }
      if (EPI <= 1) {
        *(__half2*)(OH + i0) = __floats2half2_rn(v0, v1);
        *(__half2*)(OH + i1) = __floats2half2_rn(v2, v3);
      }
    }
  }
}

// ---------------------------------------------------------------------------
// Elementwise kernels
// ---------------------------------------------------------------------------
__global__ void cvt_kernel(const float* __restrict__ x, __half* __restrict__ y) {
  long i = ((long)blockIdx.x * 256 + threadIdx.x) * 4;
  float4 v = *(const float4*)(x + i);
  __half2 lo = __floats2half2_rn(v.x, v.y);
  __half2 hi = __floats2half2_rn(v.z, v.w);
  uint2 pk;
  pk.x = *(uint32_t*)&lo;
  pk.y = *(uint32_t*)&hi;
  *(uint2*)(y + i) = pk;
}

__global__ void silu_kernel(const __half* __restrict__ gu, __half* __restrict__ ho) {
  const long m = blockIdx.y;
  const long c = ((long)blockIdx.x * 256 + threadIdx.x) * 2;
  const long base = m * (2L * IDIM);
  __half2 g2 = *(const __half2*)(gu + base + c);
  __half2 u2 = *(const __half2*)(gu + base + IDIM + c);
  float g0 = __half2float(__low2half(g2)), g1 = __half2float(__high2half(g2));
  float u0 = __half2float(__low2half(u2)), u1 = __half2float(__high2half(u2));
  float h0 = g0 / (1.f + __expf(-g0)) * u0;
  float h1 = g1 / (1.f + __expf(-g1)) * u1;
  *(__half2*)(ho + m * (long)IDIM + c) = __floats2half2_rn(h0, h1);
}

// ---------------------------------------------------------------------------
// Host driver (graph-capturable: kernel launches only)
// ---------------------------------------------------------------------------
extern "C" void kernel_launch(void* const* d_in, const int* in_sizes, int n_in,
                              void* d_out, int out_size) {
  const float* x           = (const float*)d_in[0];
  const int*   codes_attn  = (const int*)  d_in[1];
  const float* scales_attn = (const float*)d_in[2];
  const int*   codes_gu    = (const int*)  d_in[3];
  const float* scales_gu   = (const float*)d_in[4];
  const int*   codes_down  = (const int*)  d_in[5];
  const float* scales_down = (const float*)d_in[6];
  const float* lora_A_h    = (const float*)d_in[7];
  const float* lora_A_down = (const float*)d_in[8];
  const float* lora_B_attn = (const float*)d_in[9];
  const float* lora_B_gu   = (const float*)d_in[10];
  const float* lora_B_down = (const float*)d_in[11];
  (void)in_sizes; (void)n_in; (void)out_size;

  __half *xh, *Wqkv, *Wo, *Wgu, *Wd, *attn, *x1h, *gu, *hb;
  float *x1f;
  cudaGetSymbolAddress((void**)&xh,   g_xh);
  cudaGetSymbolAddress((void**)&Wqkv, g_Wqkv);
  cudaGetSymbolAddress((void**)&Wo,   g_Wo);
  cudaGetSymbolAddress((void**)&Wgu,  g_Wgu);
  cudaGetSymbolAddress((void**)&Wd,   g_Wd);
  cudaGetSymbolAddress((void**)&attn, g_attn);
  cudaGetSymbolAddress((void**)&x1h,  g_x1h);
  cudaGetSymbolAddress((void**)&x1f,  g_x1f);
  cudaGetSymbolAddress((void**)&gu,   g_gu);
  cudaGetSymbolAddress((void**)&hb,   g_hb);

  cudaFuncSetAttribute(gemm_kernel<0>, cudaFuncAttributeMaxDynamicSharedMemorySize, SMEM_GEMM);
  cudaFuncSetAttribute(gemm_kernel<1>, cudaFuncAttributeMaxDynamicSharedMemorySize, SMEM_GEMM);
  cudaFuncSetAttribute(gemm_kernel<2>, cudaFuncAttributeMaxDynamicSharedMemorySize, SMEM_GEMM);

  // x -> fp16
  cvt_kernel<<<(MDIM * (long)HDIM) / 1024, 256>>>(x, xh);

  // Dequant + LoRA fold (qkv fused with mul = 1/3)
  dq3_kernel<<<dim3(HDIM / 256, HDIM / 32), 256>>>(
      codes_attn, scales_attn, lora_A_h, lora_B_attn, Wqkv, HDIM, HDIM,
      (long)HDIM * HDIM, (long)HDIM * (HDIM / 64), (long)HDIM * RNK, 1.f / 3.f);
  dq1_kernel<<<dim3(HDIM / 1024, HDIM / 32), 256>>>(
      codes_attn + 3L * HDIM * HDIM, scales_attn + 3L * HDIM * (HDIM / 64),
      lora_A_h + 3L * RNK * HDIM, lora_B_attn + 3L * HDIM * RNK,
      Wo, HDIM, HDIM);
  dq1_kernel<<<dim3(HDIM / 1024, IDIM / 32), 256>>>(
      codes_gu, scales_gu, lora_A_h + 4L * RNK * HDIM, lora_B_gu,
      Wgu, IDIM, HDIM);
  dq1_kernel<<<dim3(HDIM / 1024, IDIM / 32), 256>>>(
      codes_gu + (long)IDIM * HDIM, scales_gu + (long)IDIM * (HDIM / 64),
      lora_A_h + 5L * RNK * HDIM, lora_B_gu + (long)IDIM * RNK,
      Wgu + (long)IDIM * HDIM, IDIM, HDIM);
  dq1_kernel<<<dim3(IDIM / 1024, HDIM / 32), 256>>>(
      codes_down, scales_down, lora_A_down, lora_B_down,
      Wd, HDIM, IDIM);

  // attn = xh @ Wqkv^T    (already = (q+k+v)/3)
  gemm_kernel<0><<<dim3(MDIM / BM, HDIM / BN), 256, SMEM_GEMM>>>(
      xh, Wqkv, nullptr, attn, nullptr, HDIM, HDIM);
  // x1 = x + attn @ Wo^T  (store fp32 + fp16)
  gemm_kernel<1><<<dim3(MDIM / BM, HDIM / BN), 256, SMEM_GEMM>>>(
      attn, Wo, x, x1h, x1f, HDIM, HDIM);
  // [g | u] = x1h @ Wgu^T
  gemm_kernel<0><<<dim3(MDIM / BM, (2 * IDIM) / BN), 256, SMEM_GEMM>>>(
      x1h, Wgu, nullptr, gu, nullptr, 2 * IDIM, HDIM);
  // h = silu(g) * u
  silu_kernel<<<dim3(IDIM / 512, MDIM), 256>>>(gu, hb);
  // out = x1 + h @ Wd^T   (fp32 to d_out)
  gemm_kernel<2><<<dim3(MDIM / BM, HDIM / BN), 256, SMEM_GEMM>>>(
      hb, Wd, x1f, nullptr, (float*)d_out, HDIM, IDIM);
}

// round 13
// speedup vs baseline: 1.2187x; 1.0653x over previous
#include <cuda_runtime.h>
#include <cuda_fp16.h>
#include <cstdint>

// ---------------------------------------------------------------------------
// Problem dims (fixed by the dataset)
// ---------------------------------------------------------------------------
#define HDIM 4096
#define IDIM 14336
#define MDIM 4096   // BT * S = 2 * 2048
#define RNK  16

__constant__ float c_nf4[16] = {
  -1.0f, -0.6961928009986877f, -0.5250730514526367f, -0.39491748809814453f,
  -0.28444138169288635f, -0.18477343022823334f, -0.09105003625154495f, 0.0f,
  0.07958029955625534f, 0.16093020141124725f, 0.24611230194568634f,
  0.33791524171829224f, 0.44070982933044434f, 0.5626170039176941f,
  0.7229568362236023f, 1.0f};

// ---------------------------------------------------------------------------
// Scratch (static __device__ arrays: allocation-free per harness rules)
// ---------------------------------------------------------------------------
__device__ __half g_xh  [(size_t)MDIM * HDIM];
__device__ __half g_Wqkv[(size_t)HDIM * HDIM];
__device__ __half g_Wo  [(size_t)HDIM * HDIM];
__device__ __half g_Wgu [(size_t)2 * IDIM * HDIM];   // interleaved: row 2j=gate_j, 2j+1=up_j
__device__ __half g_Wd  [(size_t)HDIM * IDIM];
__device__ __half g_attn[(size_t)MDIM * HDIM];
__device__ __half g_x1h [(size_t)MDIM * HDIM];
__device__ float  g_x1f [(size_t)MDIM * HDIM];
__device__ __half g_hb  [(size_t)MDIM * IDIM];

// ---------------------------------------------------------------------------
// Dequant + LoRA-fold, QKV-fused variant (3 code planes summed, mul=1/3).
// ---------------------------------------------------------------------------
__global__ void dq3_kernel(const int* __restrict__ codes,
                           const float* __restrict__ scales,
                           const float* __restrict__ Amat,   // [48, K]
                           const float* __restrict__ Bmat,   // [4, O, 16] planes
                           __half* __restrict__ W,
                           int O, int K,
                           long codePlane, long scalePlane, long bPlane,
                           float mul)
{
  constexpr int RR = 48;
  constexpr int OT = 32;
  __shared__ float sB[OT * RR];
  const int tid = threadIdx.x;         // 256 threads
  const int h0 = blockIdx.x * 256;
  const int o0 = blockIdx.y * OT;

  for (int i = tid; i < OT * RR; i += 256) {
    int oi = i / RR, r = i - oi * RR;
    sB[i] = Bmat[(long)(r >> 4) * bPlane + (long)(o0 + oi) * RNK + (r & 15)];
  }
  const int h = h0 + tid;
  float areg[RR];
  #pragma unroll
  for (int r = 0; r < RR; ++r) areg[r] = Amat[(long)r * K + h] * mul;
  __syncthreads();

  const int hb = h >> 6;
  #pragma unroll 4
  for (int oi = 0; oi < OT; ++oi) {
    const int o = o0 + oi;
    float acc = 0.f;
    #pragma unroll
    for (int j = 0; j < 3; ++j) {
      int   c = codes [(long)j * codePlane  + (long)o * K        + h];
      float s = scales[(long)j * scalePlane + (long)o * (K >> 6) + hb];
      acc += c_nf4[c & 15] * s;
    }
    acc *= mul;
    float lacc = 0.f;
    #pragma unroll
    for (int r = 0; r < RR; ++r) lacc += sB[oi * RR + r] * areg[r];
    W[(long)o * K + h] = __float2half(acc + lacc);
  }
}

// ---------------------------------------------------------------------------
// Dequant + LoRA-fold, single plane, 4 h per thread, 4-deep load rotation.
// rowStride (elements) allows interleaved output rows (gu fusion).
// ---------------------------------------------------------------------------
__global__ void dq1_kernel(const int* __restrict__ codes,
                           const float* __restrict__ scales,
                           const float* __restrict__ Amat,   // [16, K]
                           const float* __restrict__ Bmat,   // [O, 16]
                           __half* __restrict__ W,
                           int O, int K, long rowStride)
{
  constexpr int RR = 16;
  constexpr int OT = 32;
  __shared__ float sB[OT * RR];
  const int tid = threadIdx.x;         // 256 threads
  const int h0 = blockIdx.x * 1024;
  const int o0 = blockIdx.y * OT;

  for (int i = tid; i < OT * RR; i += 256) {
    int oi = i / RR, r = i - oi * RR;
    sB[i] = Bmat[(long)(o0 + oi) * RNK + r];
  }
  const int h = h0 + tid * 4;
  float4 areg[RR];
  #pragma unroll
  for (int r = 0; r < RR; ++r)
    areg[r] = *(const float4*)(Amat + (long)r * K + h);
  __syncthreads();

  const int hb = h >> 6;
  const int ks6 = K >> 6;

  int4  c[4];
  float s[4];
  #pragma unroll
  for (int j = 0; j < 4; ++j) {
    c[j] = *(const int4*)(codes + (long)(o0 + j) * K + h);
    s[j] = scales[(long)(o0 + j) * ks6 + hb];
  }

  #pragma unroll 4
  for (int oi = 0; oi < OT; ++oi) {
    const int slot = oi & 3;
    int4  cc = c[slot];
    float ss = s[slot];
    if (oi + 4 < OT) {
      c[slot] = *(const int4*)(codes + (long)(o0 + oi + 4) * K + h);
      s[slot] = scales[(long)(o0 + oi + 4) * ks6 + hb];
    }
    float v0 = c_nf4[cc.x & 15] * ss;
    float v1 = c_nf4[cc.y & 15] * ss;
    float v2 = c_nf4[cc.z & 15] * ss;
    float v3 = c_nf4[cc.w & 15] * ss;
    #pragma unroll
    for (int r = 0; r < RR; ++r) {
      float b = sB[oi * RR + r];
      v0 += b * areg[r].x;
      v1 += b * areg[r].y;
      v2 += b * areg[r].z;
      v3 += b * areg[r].w;
    }
    __half2 lo = __floats2half2_rn(v0, v1);
    __half2 hi = __floats2half2_rn(v2, v3);
    uint2 pk;
    pk.x = *(uint32_t*)&lo;
    pk.y = *(uint32_t*)&hi;
    *(uint2*)(W + (long)(o0 + oi) * rowStride + h) = pk;
  }
}

// ---------------------------------------------------------------------------
// fp16 GEMM:  C[M,N] = A[M,K] @ B[N,K]^T, fp32 accum.
// Tile 128x256x64, 8 warps (2x4), warp tile 64x64, mma.sync.m16n8k16.
// 4-stage cp.async pipeline; double-buffered LDSM frags; spread prefetch.
// EPI: 0 half(C); 1 f=resid+C f32+half; 2 f32 only; 3 silu(g)*u -> half (gu).
// ---------------------------------------------------------------------------
#define BM 128
#define BN 256
#define BK 64
#define STG 4
#define STAGE_B ((BM + BN) * BK * 2)          // 49152
#define SMEM_GEMM (STG * STAGE_B)             // 196608

__device__ __forceinline__ void cp16(uint32_t dst, const void* src) {
  asm volatile("cp.async.cg.shared.global [%0], [%1], 16;" :: "r"(dst), "l"(src));
}

__device__ __forceinline__ void gemm_load_stage(const __half* __restrict__ Ag,
                                                const __half* __restrict__ Bg,
                                                long Kdim, int m0, int n0,
                                                int lrow, int lcc, uint32_t off0,
                                                uint32_t sbase, int st, int kt)
{
  const long k0 = (long)kt * BK;
  uint32_t sA = sbase + (uint32_t)st * STAGE_B;
  uint32_t sB = sA + BM * BK * 2u;
  const __half* gA = Ag + (long)(m0 + lrow) * Kdim + k0 + lcc * 8;
  const __half* gB = Bg + (long)(n0 + lrow) * Kdim + k0 + lcc * 8;
  #pragma unroll
  for (int i = 0; i < 4; ++i)
    cp16(sA + off0 + (uint32_t)i * 4096u, gA + (long)i * 32 * Kdim);
  #pragma unroll
  for (int i = 0; i < 8; ++i)
    cp16(sB + off0 + (uint32_t)i * 4096u, gB + (long)i * 32 * Kdim);
  asm volatile("cp.async.commit_group;");
}

__device__ __forceinline__ void ld_frags(uint32_t sA, uint32_t sB,
                                         int wm, int wn, int lane, int ks,
                                         uint32_t af[4][4], uint32_t bf[8][2])
{
  #pragma unroll
  for (int mi = 0; mi < 4; ++mi) {
    int row = wm * 64 + mi * 16 + (lane & 15);
    int c3  = 2 * ks + (lane >> 4);
    uint32_t addr = sA + (uint32_t)row * 128u +
                    ((uint32_t)((c3 ^ (row & 7))) << 4);
    asm volatile("ldmatrix.sync.aligned.m8n8.x4.shared.b16 {%0,%1,%2,%3}, [%4];"
                 : "=r"(af[mi][0]), "=r"(af[mi][1]), "=r"(af[mi][2]), "=r"(af[mi][3])
                 : "r"(addr));
  }
  #pragma unroll
  for (int nb = 0; nb < 4; ++nb) {
    int row = wn * 64 + nb * 16 + (lane & 7) + ((lane >> 4) << 3);
    int c3  = 2 * ks + ((lane >> 3) & 1);
    uint32_t addr = sB + (uint32_t)row * 128u +
                    ((uint32_t)((c3 ^ (row & 7))) << 4);
    asm volatile("ldmatrix.sync.aligned.m8n8.x4.shared.b16 {%0,%1,%2,%3}, [%4];"
                 : "=r"(bf[2*nb][0]), "=r"(bf[2*nb][1]),
                   "=r"(bf[2*nb+1][0]), "=r"(bf[2*nb+1][1])
                 : "r"(addr));
  }
}

template<int EPI>
__global__ void __launch_bounds__(256, 1)
gemm_kernel(const __half* __restrict__ Ag, const __half* __restrict__ Bg,
            const float* __restrict__ Rg, __half* __restrict__ OH,
            float* __restrict__ OF, int Ndim, int Kdim)
{
  extern __shared__ __half smem[];
  const int tid  = threadIdx.x;
  const int m0   = blockIdx.x * BM;   // m fastest -> W n-band reused across wave
  const int n0   = blockIdx.y * BN;
  const uint32_t sbase = (uint32_t)__cvta_generic_to_shared(smem);
  const int warp = tid >> 5, lane = tid & 31;
  const int wm = warp & 1, wn = warp >> 1;          // 2 x 4 warps
  const int lrow = tid >> 3, lcc = tid & 7;
  const uint32_t off0 = (uint32_t)lrow * 128u +
                        ((uint32_t)(lcc ^ (lrow & 7)) << 4);
  const int KT = Kdim / BK;

  float acc[4][8][4];
  #pragma unroll
  for (int a = 0; a < 4; ++a)
    #pragma unroll
    for (int b = 0; b < 8; ++b)
      #pragma unroll
      for (int c = 0; c < 4; ++c) acc[a][b][c] = 0.f;

  gemm_load_stage(Ag, Bg, Kdim, m0, n0, lrow, lcc, off0, sbase, 0, 0);
  gemm_load_stage(Ag, Bg, Kdim, m0, n0, lrow, lcc, off0, sbase, 1, 1);
  gemm_load_stage(Ag, Bg, Kdim, m0, n0, lrow, lcc, off0, sbase, 2, 2);

  uint32_t af[2][4][4], bf[2][8][2];

  for (int kt = 0; kt < KT; ++kt) {
    asm volatile("cp.async.wait_group 2;");
    __syncthreads();

    uint32_t sA = sbase + (uint32_t)(kt & 3) * STAGE_B;
    uint32_t sB = sA + BM * BK * 2u;

    // Next-stage (kt+3) global pointers; its buffer (kt-1)&3 was consumed
    // in iter kt-1 (all ldmatrix complete before the syncthreads above).
    const bool pf = (kt + 3 < KT);
    const long pk0 = (long)(kt + 3) * BK;
    uint32_t pA = sbase + (uint32_t)((kt + 3) & 3) * STAGE_B;
    uint32_t pB = pA + BM * BK * 2u;
    const __half* gA = Ag + (long)(m0 + lrow) * Kdim + pk0 + lcc * 8;
    const __half* gB = Bg + (long)(n0 + lrow) * Kdim + pk0 + lcc * 8;

    ld_frags(sA, sB, wm, wn, lane, 0, af[0], bf[0]);

    #pragma unroll
    for (int ks = 0; ks < 4; ++ks) {
      if (ks < 3)
        ld_frags(sA, sB, wm, wn, lane, ks + 1, af[(ks + 1) & 1], bf[(ks + 1) & 1]);
      if (ks == 0 && pf) {
        #pragma unroll
        for (int i = 0; i < 4; ++i)
          cp16(pA + off0 + (uint32_t)i * 4096u, gA + (long)i * 32 * Kdim);
      }
      if (ks == 1 && pf) {
        #pragma unroll
        for (int i = 0; i < 4; ++i)
          cp16(pB + off0 + (uint32_t)i * 4096u, gB + (long)i * 32 * Kdim);
      }
      if (ks == 2 && pf) {
        #pragma unroll
        for (int i = 4; i < 8; ++i)
          cp16(pB + off0 + (uint32_t)i * 4096u, gB + (long)i * 32 * Kdim);
      }
      if (ks == 3)
        asm volatile("cp.async.commit_group;");   // empty group at tail keeps count

      const int cb = ks & 1;
      #pragma unroll
      for (int mi = 0; mi < 4; ++mi)
        #pragma unroll
        for (int ni = 0; ni < 8; ++ni)
          asm volatile("mma.sync.aligned.m16n8k16.row.col.f32.f16.f16.f32 "
                       "{%0,%1,%2,%3}, {%4,%5,%6,%7}, {%8,%9}, {%0,%1,%2,%3};"
                       : "+f"(acc[mi][ni][0]), "+f"(acc[mi][ni][1]),
                         "+f"(acc[mi][ni][2]), "+f"(acc[mi][ni][3])
                       : "r"(af[cb][mi][0]), "r"(af[cb][mi][1]),
                         "r"(af[cb][mi][2]), "r"(af[cb][mi][3]),
                         "r"(bf[cb][ni][0]), "r"(bf[cb][ni][1]));
    }
  }

  // Epilogue (registers only)
  if (EPI == 3) {
    // interleaved [g|u] columns: even col = gate, odd col = up (same j)
    const long mb2 = m0 + wm * 64 + (lane >> 2);
    const int  jb  = ((n0 + wn * 64) >> 1) + (lane & 3);
    #pragma unroll
    for (int mi = 0; mi < 4; ++mi) {
      #pragma unroll
      for (int ni = 0; ni < 8; ++ni) {
        long r = mb2 + mi * 16;
        int  j = jb + ni * 4;
        float ga = acc[mi][ni][0], ua = acc[mi][ni][1];
        float gb2 = acc[mi][ni][2], ub = acc[mi][ni][3];
        float ha = ga / (1.f + __expf(-ga)) * ua;
        float hbv = gb2 / (1.f + __expf(-gb2)) * ub;
        OH[r * (long)Ndim + j]       = __float2half(ha);
        OH[(r + 8) * (long)Ndim + j] = __float2half(hbv);
      }
    }
    return;
  }
  const long mbase = m0 + wm * 64 + (lane >> 2);
  const long nbase = n0 + wn * 64 + (lane & 3) * 2;
  #pragma unroll
  for (int mi = 0; mi < 4; ++mi) {
    #pragma unroll
    for (int ni = 0; ni < 8; ++ni) {
      long r = mbase + mi * 16;
      long c = nbase + ni * 8;
      long i0 = r * Ndim + c;
      long i1 = (r + 8) * Ndim + c;
      float v0 = acc[mi][ni][0], v1 = acc[mi][ni][1];
      float v2 = acc[mi][ni][2], v3 = acc[mi][ni][3];
      if (EPI >= 1) {
        float2 ra = *(const float2*)(Rg + i0);
        float2 rb = *(const float2*)(Rg + i1);
        v0 += ra.x; v1 += ra.y; v2 += rb.x; v3 += rb.y;
        *(float2*)(OF + i0) = make_float2(v0, v1);
        *(float2*)(OF + i1) = make_float2(v2, v3);
      }
      if (EPI <= 1) {
        *(__half2*)(OH + i0) = __floats2half2_rn(v0, v1);
        *(__half2*)(OH + i1) = __floats2half2_rn(v2, v3);
      }
    }
  }
}

// ---------------------------------------------------------------------------
// Elementwise
// ---------------------------------------------------------------------------
__global__ void cvt_kernel(const float* __restrict__ x, __half* __restrict__ y) {
  long i = ((long)blockIdx.x * 256 + threadIdx.x) * 4;
  float4 v = *(const float4*)(x + i);
  __half2 lo = __floats2half2_rn(v.x, v.y);
  __half2 hi = __floats2half2_rn(v.z, v.w);
  uint2 pk;
  pk.x = *(uint32_t*)&lo;
  pk.y = *(uint32_t*)&hi;
  *(uint2*)(y + i) = pk;
}

// ---------------------------------------------------------------------------
// Host driver (graph-capturable; two streams forked/joined with events)
// ---------------------------------------------------------------------------
extern "C" void kernel_launch(void* const* d_in, const int* in_sizes, int n_in,
                              void* d_out, int out_size) {
  const float* x           = (const float*)d_in[0];
  const int*   codes_attn  = (const int*)  d_in[1];
  const float* scales_attn = (const float*)d_in[2];
  const int*   codes_gu    = (const int*)  d_in[3];
  const float* scales_gu   = (const float*)d_in[4];
  const int*   codes_down  = (const int*)  d_in[5];
  const float* scales_down = (const float*)d_in[6];
  const float* lora_A_h    = (const float*)d_in[7];
  const float* lora_A_down = (const float*)d_in[8];
  const float* lora_B_attn = (const float*)d_in[9];
  const float* lora_B_gu   = (const float*)d_in[10];
  const float* lora_B_down = (const float*)d_in[11];
  (void)in_sizes; (void)n_in; (void)out_size;

  __half *xh, *Wqkv, *Wo, *Wgu, *Wd, *attn, *x1h, *hb;
  float *x1f;
  cudaGetSymbolAddress((void**)&xh,   g_xh);
  cudaGetSymbolAddress((void**)&Wqkv, g_Wqkv);
  cudaGetSymbolAddress((void**)&Wo,   g_Wo);
  cudaGetSymbolAddress((void**)&Wgu,  g_Wgu);
  cudaGetSymbolAddress((void**)&Wd,   g_Wd);
  cudaGetSymbolAddress((void**)&attn, g_attn);
  cudaGetSymbolAddress((void**)&x1h,  g_x1h);
  cudaGetSymbolAddress((void**)&x1f,  g_x1f);
  cudaGetSymbolAddress((void**)&hb,   g_hb);

  cudaFuncSetAttribute(gemm_kernel<0>, cudaFuncAttributeMaxDynamicSharedMemorySize, SMEM_GEMM);
  cudaFuncSetAttribute(gemm_kernel<1>, cudaFuncAttributeMaxDynamicSharedMemorySize, SMEM_GEMM);
  cudaFuncSetAttribute(gemm_kernel<2>, cudaFuncAttributeMaxDynamicSharedMemorySize, SMEM_GEMM);
  cudaFuncSetAttribute(gemm_kernel<3>, cudaFuncAttributeMaxDynamicSharedMemorySize, SMEM_GEMM);

  // One-time side stream + events (created on first (correctness) call,
  // outside graph capture; reused deterministically every call).
  static cudaStream_t s1 = nullptr;
  static cudaEvent_t evFork = nullptr, evJoin = nullptr;
  if (s1 == nullptr) {
    cudaStreamCreateWithFlags(&s1, cudaStreamNonBlocking);
    cudaEventCreateWithFlags(&evFork, cudaEventDisableTiming);
    cudaEventCreateWithFlags(&evJoin, cudaEventDisableTiming);
  }

  // ---- fork: independent weight dequants on s1 -------------------------
  cudaEventRecord(evFork, 0);
  cudaStreamWaitEvent(s1, evFork, 0);

  dq1_kernel<<<dim3(HDIM / 1024, HDIM / 32), 256, 0, s1>>>(
      codes_attn + 3L * HDIM * HDIM, scales_attn + 3L * HDIM * (HDIM / 64),
      lora_A_h + 3L * RNK * HDIM, lora_B_attn + 3L * HDIM * RNK,
      Wo, HDIM, HDIM, HDIM);
  dq1_kernel<<<dim3(HDIM / 1024, IDIM / 32), 256, 0, s1>>>(
      codes_gu, scales_gu, lora_A_h + 4L * RNK * HDIM, lora_B_gu,
      Wgu, IDIM, HDIM, 2L * HDIM);                       // gate -> rows 2j
  dq1_kernel<<<dim3(HDIM / 1024, IDIM / 32), 256, 0, s1>>>(
      codes_gu + (long)IDIM * HDIM, scales_gu + (long)IDIM * (HDIM / 64),
      lora_A_h + 5L * RNK * HDIM, lora_B_gu + (long)IDIM * RNK,
      Wgu + HDIM, IDIM, HDIM, 2L * HDIM);                // up -> rows 2j+1
  dq1_kernel<<<dim3(IDIM / 1024, HDIM / 32), 256, 0, s1>>>(
      codes_down, scales_down, lora_A_down, lora_B_down,
      Wd, HDIM, IDIM, IDIM);
  cudaEventRecord(evJoin, s1);

  // ---- main stream: attn path ------------------------------------------
  cvt_kernel<<<(MDIM * (long)HDIM) / 1024, 256>>>(x, xh);
  dq3_kernel<<<dim3(HDIM / 256, HDIM / 32), 256>>>(
      codes_attn, scales_attn, lora_A_h, lora_B_attn, Wqkv, HDIM, HDIM,
      (long)HDIM * HDIM, (long)HDIM * (HDIM / 64), (long)HDIM * RNK, 1.f / 3.f);

  // attn = xh @ Wqkv^T   (already = (q+k+v)/3)
  gemm_kernel<0><<<dim3(MDIM / BM, HDIM / BN), 256, SMEM_GEMM>>>(
      xh, Wqkv, nullptr, attn, nullptr, HDIM, HDIM);

  // ---- join: all s1 dequants done before GEMM2 --------------------------
  cudaStreamWaitEvent(0, evJoin, 0);

  // x1 = x + attn @ Wo^T  (store fp32 + fp16)
  gemm_kernel<1><<<dim3(MDIM / BM, HDIM / BN), 256, SMEM_GEMM>>>(
      attn, Wo, x, x1h, x1f, HDIM, HDIM);
  // hb = silu(g) * u  fused into the gu GEMM (interleaved Wgu)
  gemm_kernel<3><<<dim3(MDIM / BM, (2 * IDIM) / BN), 256, SMEM_GEMM>>>(
      x1h, Wgu, nullptr, hb, nullptr, IDIM, HDIM);
  // out = x1 + hb @ Wd^T   (fp32 to d_out)
  gemm_kernel<2><<<dim3(MDIM / BM, HDIM / BN), 256, SMEM_GEMM>>>(
      hb, Wd, x1f, nullptr, (float*)d_out, HDIM, IDIM);
}